// round 9
// baseline (speedup 1.0000x reference)
#include <cuda_runtime.h>
#include <float.h>
#include <stdint.h>

#define DIM 128
#define N_SAMPLES 8192
#define N_EMBED 10000
#define N_EMBED_PAD 10240
#define TM 64
#define TN 64
#define BSTRIDE 72            // 64 + 8 pad: all 32 B-frag lanes hit distinct banks
#define THREADS 256
#define NSLICE 16
#define SLICE_W 640
#define NCH 10                // chunks of TN per slice

typedef unsigned long long u64;

__device__ float g_cnorm[N_EMBED_PAD];          // |c_j|^2, -1e30 for pad
__device__ u64   g_best[N_SAMPLES];             // packed (enc(val)<<32 | ~j)
__device__ float g_bhi[DIM * N_EMBED_PAD];      // tf32 hi of cluster_mean
__device__ float g_blo[DIM * N_EMBED_PAD];      // tf32 lo residual

__device__ __forceinline__ uint32_t tf32_rna(float v) {
    uint32_t u; asm("cvt.rna.tf32.f32 %0, %1;" : "=r"(u) : "f"(v)); return u;
}
__device__ __forceinline__ unsigned smem_u32(const void* p) {
    return (unsigned)__cvta_generic_to_shared(p);
}
__device__ __forceinline__ void cp16(unsigned dst, const void* src) {
    asm volatile("cp.async.cg.shared.global [%0], [%1], 16;"
                 :: "r"(dst), "l"(src));
}
// Order-preserving encode: larger val -> larger u64; equal val -> smaller j wins.
__device__ __forceinline__ u64 enc_best(float v, int j) {
    unsigned b = __float_as_uint(v);
    b = ((int)b < 0) ? ~b : (b | 0x80000000u);
    return ((u64)b << 32) | (unsigned)(~j);
}
// D(16x8,f32) += A(16x8,tf32,row) * B(8x8,tf32,col)
__device__ __forceinline__ void mma_tf32(float* d, float4 a, float b0, float b1) {
    asm volatile(
        "mma.sync.aligned.m16n8k8.row.col.f32.tf32.tf32.f32 "
        "{%0,%1,%2,%3}, {%4,%5,%6,%7}, {%8,%9}, {%0,%1,%2,%3};"
        : "+f"(d[0]), "+f"(d[1]), "+f"(d[2]), "+f"(d[3])
        : "r"(__float_as_uint(a.x)), "r"(__float_as_uint(a.y)),
          "r"(__float_as_uint(a.z)), "r"(__float_as_uint(a.w)),
          "r"(__float_as_uint(b0)),  "r"(__float_as_uint(b1)));
}

// ---------------- prep kernels ----------------
__global__ void cnorm_kernel(const float* __restrict__ cm) {
    __shared__ float red[4][64];
    const int tid = threadIdx.x;
    const int jl  = tid & 63;
    const int dc  = tid >> 6;
    const int j   = blockIdx.x * 64 + jl;
    const int gid = blockIdx.x * 256 + tid;
    if (gid < N_SAMPLES) g_best[gid] = 0ull;
    float s = 0.f;
    if (j < N_EMBED) {
#pragma unroll 8
        for (int dd = 0; dd < 32; dd++) {
            float v = cm[(dc * 32 + dd) * N_EMBED + j];
            s += v * v;
        }
    }
    red[dc][jl] = s;
    __syncthreads();
    if (dc == 0) {
        float t = red[0][jl] + red[1][jl] + red[2][jl] + red[3][jl];
        g_cnorm[j] = (j < N_EMBED) ? t : -1e30f;
    }
}

// Split cluster_mean into tf32 hi/lo, padded [DIM][N_EMBED_PAD] (zero pad).
__global__ void prep_b_kernel(const float* __restrict__ cm) {
    int idx = blockIdx.x * 256 + threadIdx.x;
    if (idx >= DIM * N_EMBED_PAD) return;
    int k = idx / N_EMBED_PAD, j = idx - k * N_EMBED_PAD;
    float v = (j < N_EMBED) ? cm[k * N_EMBED + j] : 0.f;
    float hf = __uint_as_float(tf32_rna(v));
    g_bhi[idx] = hf;
    g_blo[idx] = __uint_as_float(tf32_rna(v - hf));
}

// ---------------- main mma kernel ----------------
// smem: Ahi[4mt][16ks][32lane][4] 32KB | Alo 32KB | B ring 2 x (hi+lo 128xBSTRIDE)
#define AFRAG_FLOATS (4 * 16 * 32 * 4)
#define BHALF_FLOATS (128 * BSTRIDE)
#define SMEM_FLOATS  (2 * AFRAG_FLOATS + 2 * 2 * BHALF_FLOATS)

__global__ __launch_bounds__(THREADS, 1)
void quantize_kernel(const float* __restrict__ A) {
    extern __shared__ float smf[];
    float* Ahi  = smf;
    float* Alo  = smf + AFRAG_FLOATS;
    float* Bbuf = smf + 2 * AFRAG_FLOATS;

    const int tid  = threadIdx.x;
    const int lane = tid & 31;
    const int sy   = tid >> 5;           // 8 warps: 2 m-groups x 4 n-groups
    const int wm   = sy >> 2;            // 0..1
    const int wn   = sy & 3;             // 0..3
    const int n0w  = wn * 16;
    const int mtg0 = wm * 2;             // warp's first m16-tile (of 4 in CTA)

    const int mt  = blockIdx.x & 127;
    const int sl  = blockIdx.x >> 7;
    const int m0  = mt * TM;
    const int j00 = sl * SLICE_W;

    auto issueB = [&](int t) {
        const int j0 = j00 + t * TN;
        float* dst = Bbuf + (t & 1) * (2 * BHALF_FLOATS);
        for (int i = tid; i < 4096; i += THREADS) {   // 16 iters
            int sel = i >> 11;            // 0 = hi, 1 = lo
            int k   = (i >> 4) & 127;
            int jj  = (i & 15) * 4;
            const float* src = (sel ? g_blo : g_bhi)
                             + (size_t)k * N_EMBED_PAD + j0 + jj;
            cp16(smem_u32(dst + sel * BHALF_FLOATS + k * BSTRIDE + jj), src);
        }
        asm volatile("cp.async.commit_group;");
    };

    issueB(0);
    issueB(1);

    // A prep: split -2x into tf32 hi/lo, fragment-major (1 LDS.128 per frag).
    for (int i = tid; i < 2048; i += THREADS) {      // 8 iters
        int li = i & 31;
        int ks = (i >> 5) & 15;
        int mq = i >> 9;                  // m16-tile 0..3
        int r = li >> 2, c = li & 3;
        int row = m0 + mq * 16 + r;
        int col = ks * 8 + c;
        float v0 = -2.f * A[row * DIM + col];
        float v1 = -2.f * A[(row + 8) * DIM + col];
        float v2 = -2.f * A[row * DIM + col + 4];
        float v3 = -2.f * A[(row + 8) * DIM + col + 4];
        float h0 = __uint_as_float(tf32_rna(v0));
        float h1 = __uint_as_float(tf32_rna(v1));
        float h2 = __uint_as_float(tf32_rna(v2));
        float h3 = __uint_as_float(tf32_rna(v3));
        int base = ((mq * 16 + ks) * 32 + li) * 4;
        *(float4*)&Ahi[base] = make_float4(h0, h1, h2, h3);
        *(float4*)&Alo[base] = make_float4(
            __uint_as_float(tf32_rna(v0 - h0)), __uint_as_float(tf32_rna(v1 - h1)),
            __uint_as_float(tf32_rna(v2 - h2)), __uint_as_float(tf32_rna(v3 - h3)));
    }

    float best[4];
    int   bestj[4];
#pragma unroll
    for (int i = 0; i < 4; i++) { best[i] = -FLT_MAX; bestj[i] = 0; }

    const int brow = lane & 3;           // B frag k-offset
    const int bcol = lane >> 2;          // B frag n-offset

    for (int t = 0; t < NCH; t++) {
        if (t < NCH - 1) asm volatile("cp.async.wait_group 1;");
        else             asm volatile("cp.async.wait_group 0;");
        __syncthreads();                 // chunk t + A frags resident

        const float* bh = Bbuf + (t & 1) * (2 * BHALF_FLOATS);
        const float* bl = bh + BHALF_FLOATS;
        const int j0 = j00 + t * TN;

        // 12 independent acc chains: [pass][mq][nt][4], zero-init; cnorm added
        // at reduction. No RAW between mmas within a ks step.
        float acch[2][2][4], accm[2][2][4], accl[2][2][4];
#pragma unroll
        for (int mq = 0; mq < 2; mq++)
#pragma unroll
            for (int nt = 0; nt < 2; nt++)
#pragma unroll
                for (int e = 0; e < 4; e++) {
                    acch[mq][nt][e] = 0.f;
                    accm[mq][nt][e] = 0.f;
                    accl[mq][nt][e] = 0.f;
                }

#pragma unroll 8
        for (int ks = 0; ks < 16; ks++) {
            float4 ah0 = *(const float4*)&Ahi[(((mtg0 + 0) * 16 + ks) * 32 + lane) * 4];
            float4 ah1 = *(const float4*)&Ahi[(((mtg0 + 1) * 16 + ks) * 32 + lane) * 4];
            float4 al0 = *(const float4*)&Alo[(((mtg0 + 0) * 16 + ks) * 32 + lane) * 4];
            float4 al1 = *(const float4*)&Alo[(((mtg0 + 1) * 16 + ks) * 32 + lane) * 4];
            int kr = ks * 8 + brow;
            float bh00 = bh[kr * BSTRIDE + n0w + bcol];
            float bh01 = bh[(kr + 4) * BSTRIDE + n0w + bcol];
            float bh10 = bh[kr * BSTRIDE + n0w + 8 + bcol];
            float bh11 = bh[(kr + 4) * BSTRIDE + n0w + 8 + bcol];
            float bl00 = bl[kr * BSTRIDE + n0w + bcol];
            float bl01 = bl[(kr + 4) * BSTRIDE + n0w + bcol];
            float bl10 = bl[kr * BSTRIDE + n0w + 8 + bcol];
            float bl11 = bl[(kr + 4) * BSTRIDE + n0w + 8 + bcol];

            mma_tf32(acch[0][0], ah0, bh00, bh01);
            mma_tf32(acch[1][0], ah1, bh00, bh01);
            mma_tf32(acch[0][1], ah0, bh10, bh11);
            mma_tf32(acch[1][1], ah1, bh10, bh11);
            mma_tf32(accm[0][0], al0, bh00, bh01);
            mma_tf32(accm[1][0], al1, bh00, bh01);
            mma_tf32(accm[0][1], al0, bh10, bh11);
            mma_tf32(accm[1][1], al1, bh10, bh11);
            mma_tf32(accl[0][0], ah0, bl00, bl01);
            mma_tf32(accl[1][0], ah1, bl00, bl01);
            mma_tf32(accl[0][1], ah0, bl10, bl11);
            mma_tf32(accl[1][1], ah1, bl10, bl11);
        }

        // Reduce passes + cnorm, then running argmax (ascending j preserved).
#pragma unroll
        for (int nt = 0; nt < 2; nt++) {
            int c0 = j0 + n0w + nt * 8 + 2 * (lane & 3);
            float cn0 = __ldg(&g_cnorm[c0]);
            float cn1 = __ldg(&g_cnorm[c0 + 1]);
#pragma unroll
            for (int mq = 0; mq < 2; mq++) {
#pragma unroll
                for (int rb = 0; rb < 2; rb++) {
                    int slot = mq * 2 + rb;
                    float v0 = cn0 + (acch[mq][nt][rb * 2 + 0]
                             + accm[mq][nt][rb * 2 + 0] + accl[mq][nt][rb * 2 + 0]);
                    float v1 = cn1 + (acch[mq][nt][rb * 2 + 1]
                             + accm[mq][nt][rb * 2 + 1] + accl[mq][nt][rb * 2 + 1]);
                    if (v0 > best[slot]) { best[slot] = v0; bestj[slot] = c0; }
                    if (v1 > best[slot]) { best[slot] = v1; bestj[slot] = c0 + 1; }
                }
            }
        }

        __syncthreads();                 // all warps done with slot (t&1)
        if (t + 2 < NCH) issueB(t + 2);
    }

    // Reduce across the 4 lanes of each quad (same rows), then global merge.
#pragma unroll
    for (int s = 0; s < 4; s++) {
        float v  = best[s];
        int   bj = bestj[s];
#pragma unroll
        for (int off = 1; off < 4; off <<= 1) {
            float v2 = __shfl_xor_sync(0xFFFFFFFFu, v, off);
            int   j2 = __shfl_xor_sync(0xFFFFFFFFu, bj, off);
            if (v2 > v || (v2 == v && j2 < bj)) { v = v2; bj = j2; }
        }
        if ((lane & 3) == 0) {
            int mq = s >> 1, rb = s & 1;
            int row = m0 + (mtg0 + mq) * 16 + (lane >> 2) + rb * 8;
            atomicMax(&g_best[row], enc_best(v, bj));
        }
    }
}

// Merge results: gather quantize vector, write index + per-row MSE.
__global__ void combine_kernel(const float* __restrict__ A,
                               const float* __restrict__ Bm,
                               float* __restrict__ out) {
    const int w = threadIdx.x >> 5, lane = threadIdx.x & 31;
    const int s = blockIdx.x * 8 + w;
    const int j = (int)(unsigned)(~(unsigned)g_best[s]);
    float sum = 0.f;
#pragma unroll
    for (int r = 0; r < 4; r++) {
        const int d = lane + r * 32;
        float q = __ldg(&Bm[d * N_EMBED + j]);
        out[s * DIM + d] = q;
        float x = A[s * DIM + d];
        float t = x - q;
        sum += t * t;
    }
#pragma unroll
    for (int off = 16; off > 0; off >>= 1)
        sum += __shfl_xor_sync(0xFFFFFFFFu, sum, off);
    if (lane == 0) {
        out[N_SAMPLES * DIM + s] = (float)j;
        out[N_SAMPLES * (DIM + 1) + s] = sum * (1.0f / DIM);
    }
}

extern "C" void kernel_launch(void* const* d_in, const int* in_sizes, int n_in,
                              void* d_out, int out_size) {
    const float* A  = (const float*)d_in[0];   // inputs [8192,128]
    const float* Bm = (const float*)d_in[1];   // cluster_mean [128,10000]
    if (n_in >= 2 && in_sizes[0] == DIM * N_EMBED) {  // defensive order check
        const float* t = A; A = Bm; Bm = t;
    }
    float* out = (float*)d_out;

    cnorm_kernel<<<N_EMBED_PAD / 64, 256>>>(Bm);
    prep_b_kernel<<<DIM * N_EMBED_PAD / 256, 256>>>(Bm);

    const int smem_bytes = SMEM_FLOATS * (int)sizeof(float);   // 208KB
    static int attr_set = 0;
    if (!attr_set) {
        cudaFuncSetAttribute(quantize_kernel,
                             cudaFuncAttributeMaxDynamicSharedMemorySize, smem_bytes);
        attr_set = 1;
    }
    quantize_kernel<<<128 * NSLICE, THREADS, smem_bytes>>>(A);
    combine_kernel<<<N_SAMPLES / 8, 256>>>(A, Bm, out);
}

// round 10
// speedup vs baseline: 2.1339x; 2.1339x over previous
#include <cuda_runtime.h>
#include <float.h>
#include <stdint.h>

#define DIM 128
#define N_SAMPLES 8192
#define N_EMBED 10000
#define N_EMBED_PAD 10240
#define TM 64
#define TN 64
#define BSTRIDE 72            // words; 72%32=8 -> B LDS.32 conflict-free
#define THREADS 256
#define NSLICE 16
#define SLICE_W 640
#define NCH 10                // chunks of TN per slice

typedef unsigned long long u64;

__device__ float    g_cnorm[N_EMBED_PAD];         // |c_j|^2, -1e30 for pad
__device__ u64      g_best[N_SAMPLES];            // packed (enc(val)<<32 | ~j)
__device__ uint32_t g_bhi16[(DIM / 2) * N_EMBED_PAD];  // fp16x2 hi of cm, [k/2][j]
__device__ uint32_t g_blo16[(DIM / 2) * N_EMBED_PAD];  // fp16x2 lo residual

__device__ __forceinline__ unsigned smem_u32(const void* p) {
    return (unsigned)__cvta_generic_to_shared(p);
}
__device__ __forceinline__ void cp16(unsigned dst, const void* src) {
    asm volatile("cp.async.cg.shared.global [%0], [%1], 16;"
                 :: "r"(dst), "l"(src));
}
// Order-preserving encode: larger val -> larger u64; equal val -> smaller j wins.
__device__ __forceinline__ u64 enc_best(float v, int j) {
    unsigned b = __float_as_uint(v);
    b = ((int)b < 0) ? ~b : (b | 0x80000000u);
    return ((u64)b << 32) | (unsigned)(~j);
}
// Split (x, y) into fp16 hi pair (packed, x low) and fp16 lo-residual pair.
__device__ __forceinline__ void hsplit2(float x, float y, uint32_t& hw, uint32_t& lw) {
    unsigned short hx, hy, lx, ly;
    float fx, fy;
    asm("cvt.rn.f16.f32 %0, %1;" : "=h"(hx) : "f"(x));
    asm("cvt.f32.f16 %0, %1;"    : "=f"(fx) : "h"(hx));
    asm("cvt.rn.f16.f32 %0, %1;" : "=h"(lx) : "f"(x - fx));
    asm("cvt.rn.f16.f32 %0, %1;" : "=h"(hy) : "f"(y));
    asm("cvt.f32.f16 %0, %1;"    : "=f"(fy) : "h"(hy));
    asm("cvt.rn.f16.f32 %0, %1;" : "=h"(ly) : "f"(y - fy));
    hw = (uint32_t)hx | ((uint32_t)hy << 16);
    lw = (uint32_t)lx | ((uint32_t)ly << 16);
}
// D(16x8,f32) += A(16x16,f16,row) * B(16x8,f16,col)
__device__ __forceinline__ void mma_f16(float* d, uint4 a, uint32_t b0, uint32_t b1) {
    asm volatile(
        "mma.sync.aligned.m16n8k16.row.col.f32.f16.f16.f32 "
        "{%0,%1,%2,%3}, {%4,%5,%6,%7}, {%8,%9}, {%0,%1,%2,%3};"
        : "+f"(d[0]), "+f"(d[1]), "+f"(d[2]), "+f"(d[3])
        : "r"(a.x), "r"(a.y), "r"(a.z), "r"(a.w), "r"(b0), "r"(b1));
}

// ---------------- prep kernels ----------------
__global__ void cnorm_kernel(const float* __restrict__ cm) {
    __shared__ float red[4][64];
    const int tid = threadIdx.x;
    const int jl  = tid & 63;
    const int dc  = tid >> 6;
    const int j   = blockIdx.x * 64 + jl;
    const int gid = blockIdx.x * 256 + tid;
    if (gid < N_SAMPLES) g_best[gid] = 0ull;
    float s = 0.f;
    if (j < N_EMBED) {
#pragma unroll 8
        for (int dd = 0; dd < 32; dd++) {
            float v = cm[(dc * 32 + dd) * N_EMBED + j];
            s += v * v;
        }
    }
    red[dc][jl] = s;
    __syncthreads();
    if (dc == 0) {
        float t = red[0][jl] + red[1][jl] + red[2][jl] + red[3][jl];
        g_cnorm[j] = (j < N_EMBED) ? t : -1e30f;
    }
}

// Split cluster_mean into fp16 hi/lo, packed k-pairs: word(kp,j) = {k=2kp, k=2kp+1}.
__global__ void prep_b_kernel(const float* __restrict__ cm) {
    int idx = blockIdx.x * 256 + threadIdx.x;
    if (idx >= (DIM / 2) * N_EMBED_PAD) return;
    int kp = idx / N_EMBED_PAD, j = idx - kp * N_EMBED_PAD;
    float v0 = (j < N_EMBED) ? cm[(2 * kp) * N_EMBED + j] : 0.f;
    float v1 = (j < N_EMBED) ? cm[(2 * kp + 1) * N_EMBED + j] : 0.f;
    uint32_t hw, lw;
    hsplit2(v0, v1, hw, lw);
    g_bhi16[idx] = hw;
    g_blo16[idx] = lw;
}

// ---------------- main mma kernel ----------------
// smem (words): Ahi[4mt][8ks][32lane][4] = 4096 | Alo 4096 | B ring 2 x 9216
#define AW     4096
#define BHALF  (64 * BSTRIDE)     // 4608 words
#define BBUF   (2 * BHALF)        // 9216 words (hi + lo)
#define SMEM_WORDS (2 * AW + 2 * BBUF)   // 26624 words = 104KB

__global__ __launch_bounds__(THREADS, 2)
void quantize_kernel(const float* __restrict__ A) {
    extern __shared__ uint32_t smw[];
    uint32_t* Aw = smw;                 // hi at 0, lo at AW
    uint32_t* Bw = smw + 2 * AW;

    const int tid  = threadIdx.x;
    const int lane = tid & 31;
    const int sy   = tid >> 5;           // 8 warps: 2 m-groups x 4 n-groups
    const int wm   = sy >> 2;
    const int wn   = sy & 3;
    const int n0w  = wn * 16;
    const int mtg0 = wm * 2;             // warp's first m16-tile (of 4 in CTA)
    const int tig  = lane & 3;
    const int bcol = lane >> 2;

    const int mt  = blockIdx.x & 127;
    const int sl  = blockIdx.x >> 7;
    const int m0  = mt * TM;
    const int j00 = sl * SLICE_W;

    auto issueB = [&](int t) {
        const int j0 = j00 + t * TN;
        uint32_t* dst = Bw + (t & 1) * BBUF;
        for (int i = tid; i < 2048; i += THREADS) {   // 8 iters
            int sel = i >> 10;            // 0 = hi, 1 = lo
            int kp  = (i >> 4) & 63;
            int jj  = (i & 15) * 4;
            const uint32_t* src = (sel ? g_blo16 : g_bhi16)
                                + (size_t)kp * N_EMBED_PAD + j0 + jj;
            cp16(smem_u32(dst + sel * BHALF + kp * BSTRIDE + jj), src);
        }
        asm volatile("cp.async.commit_group;");
    };

    issueB(0);
    issueB(1);

    // A prep: split -2x into fp16 hi/lo, fragment-major (1 LDS.128 per frag).
    for (int i = tid; i < 1024; i += THREADS) {      // 4 iters
        int li = i & 31;
        int ks = (i >> 5) & 7;
        int mq = i >> 8;                  // m16-tile 0..3
        int r = li >> 2, tg = li & 3;
        int row0 = m0 + mq * 16 + r;
        int c0 = ks * 16 + 2 * tg;
        const float* A0 = A + (size_t)row0 * DIM;
        const float* A1 = A0 + 8 * DIM;
        uint32_t h0, l0, h1, l1, h2, l2, h3, l3;
        hsplit2(-2.f * A0[c0],     -2.f * A0[c0 + 1], h0, l0);
        hsplit2(-2.f * A1[c0],     -2.f * A1[c0 + 1], h1, l1);
        hsplit2(-2.f * A0[c0 + 8], -2.f * A0[c0 + 9], h2, l2);
        hsplit2(-2.f * A1[c0 + 8], -2.f * A1[c0 + 9], h3, l3);
        int base = ((mq * 8 + ks) * 32 + li) * 4;
        *(uint4*)&Aw[base]      = make_uint4(h0, h1, h2, h3);
        *(uint4*)&Aw[AW + base] = make_uint4(l0, l1, l2, l3);
    }

    float best[4];
    int   bestj[4];
#pragma unroll
    for (int i = 0; i < 4; i++) { best[i] = -FLT_MAX; bestj[i] = 0; }

    for (int t = 0; t < NCH; t++) {
        if (t < NCH - 1) asm volatile("cp.async.wait_group 1;");
        else             asm volatile("cp.async.wait_group 0;");
        __syncthreads();                 // chunk t + A frags resident

        const uint32_t* bh = Bw + (t & 1) * BBUF;
        const uint32_t* bl = bh + BHALF;
        const int j0 = j00 + t * TN;

        // acc[mq][nt][4], initialized with cnorm (cols 2*tig + {0,1}).
        float acc[2][2][4];
#pragma unroll
        for (int nt = 0; nt < 2; nt++) {
            int c0 = j0 + n0w + nt * 8 + 2 * tig;
            float cn0 = __ldg(&g_cnorm[c0]);
            float cn1 = __ldg(&g_cnorm[c0 + 1]);
#pragma unroll
            for (int mq = 0; mq < 2; mq++) {
                acc[mq][nt][0] = cn0; acc[mq][nt][1] = cn1;
                acc[mq][nt][2] = cn0; acc[mq][nt][3] = cn1;
            }
        }

#pragma unroll
        for (int ks = 0; ks < 8; ks++) {
            uint4 ah0 = *(const uint4*)&Aw[(((mtg0 + 0) * 8 + ks) * 32 + lane) * 4];
            uint4 ah1 = *(const uint4*)&Aw[(((mtg0 + 1) * 8 + ks) * 32 + lane) * 4];
            uint4 al0 = *(const uint4*)&Aw[AW + (((mtg0 + 0) * 8 + ks) * 32 + lane) * 4];
            uint4 al1 = *(const uint4*)&Aw[AW + (((mtg0 + 1) * 8 + ks) * 32 + lane) * 4];
            int kp0 = ks * 8 + tig;
            uint32_t bh00 = bh[kp0 * BSTRIDE + n0w + bcol];
            uint32_t bh01 = bh[(kp0 + 4) * BSTRIDE + n0w + bcol];
            uint32_t bh10 = bh[kp0 * BSTRIDE + n0w + 8 + bcol];
            uint32_t bh11 = bh[(kp0 + 4) * BSTRIDE + n0w + 8 + bcol];
            uint32_t bl00 = bl[kp0 * BSTRIDE + n0w + bcol];
            uint32_t bl01 = bl[(kp0 + 4) * BSTRIDE + n0w + bcol];
            uint32_t bl10 = bl[kp0 * BSTRIDE + n0w + 8 + bcol];
            uint32_t bl11 = bl[(kp0 + 4) * BSTRIDE + n0w + 8 + bcol];

            mma_f16(acc[0][0], ah0, bh00, bh01);
            mma_f16(acc[1][0], ah1, bh00, bh01);
            mma_f16(acc[0][1], ah0, bh10, bh11);
            mma_f16(acc[1][1], ah1, bh10, bh11);
            mma_f16(acc[0][0], al0, bh00, bh01);
            mma_f16(acc[1][0], al1, bh00, bh01);
            mma_f16(acc[0][1], al0, bh10, bh11);
            mma_f16(acc[1][1], al1, bh10, bh11);
            mma_f16(acc[0][0], ah0, bl00, bl01);
            mma_f16(acc[1][0], ah1, bl00, bl01);
            mma_f16(acc[0][1], ah0, bl10, bl11);
            mma_f16(acc[1][1], ah1, bl10, bl11);
        }

        // Running argmax. Ascending j + strict '>' keeps first-occurrence.
#pragma unroll
        for (int nt = 0; nt < 2; nt++) {
            int c0 = j0 + n0w + nt * 8 + 2 * tig;
#pragma unroll
            for (int mq = 0; mq < 2; mq++) {
#pragma unroll
                for (int rb = 0; rb < 2; rb++) {
                    int slot = mq * 2 + rb;
                    float v0 = acc[mq][nt][rb * 2 + 0];
                    float v1 = acc[mq][nt][rb * 2 + 1];
                    if (v0 > best[slot]) { best[slot] = v0; bestj[slot] = c0; }
                    if (v1 > best[slot]) { best[slot] = v1; bestj[slot] = c0 + 1; }
                }
            }
        }

        __syncthreads();                 // all warps done with slot (t&1)
        if (t + 2 < NCH) issueB(t + 2);
    }

    // Reduce across the 4 lanes of each quad (same rows), then global merge.
#pragma unroll
    for (int s = 0; s < 4; s++) {
        float v  = best[s];
        int   bj = bestj[s];
#pragma unroll
        for (int off = 1; off < 4; off <<= 1) {
            float v2 = __shfl_xor_sync(0xFFFFFFFFu, v, off);
            int   j2 = __shfl_xor_sync(0xFFFFFFFFu, bj, off);
            if (v2 > v || (v2 == v && j2 < bj)) { v = v2; bj = j2; }
        }
        if ((lane & 3) == 0) {
            int mq = s >> 1, rb = s & 1;
            int row = m0 + (mtg0 + mq) * 16 + (lane >> 2) + rb * 8;
            atomicMax(&g_best[row], enc_best(v, bj));
        }
    }
}

// Merge results: gather quantize vector, write index + per-row MSE.
__global__ void combine_kernel(const float* __restrict__ A,
                               const float* __restrict__ Bm,
                               float* __restrict__ out) {
    const int w = threadIdx.x >> 5, lane = threadIdx.x & 31;
    const int s = blockIdx.x * 8 + w;
    const int j = (int)(unsigned)(~(unsigned)g_best[s]);
    float sum = 0.f;
#pragma unroll
    for (int r = 0; r < 4; r++) {
        const int d = lane + r * 32;
        float q = __ldg(&Bm[d * N_EMBED + j]);
        out[s * DIM + d] = q;
        float x = A[s * DIM + d];
        float t = x - q;
        sum += t * t;
    }
#pragma unroll
    for (int off = 16; off > 0; off >>= 1)
        sum += __shfl_xor_sync(0xFFFFFFFFu, sum, off);
    if (lane == 0) {
        out[N_SAMPLES * DIM + s] = (float)j;
        out[N_SAMPLES * (DIM + 1) + s] = sum * (1.0f / DIM);
    }
}

extern "C" void kernel_launch(void* const* d_in, const int* in_sizes, int n_in,
                              void* d_out, int out_size) {
    const float* A  = (const float*)d_in[0];   // inputs [8192,128]
    const float* Bm = (const float*)d_in[1];   // cluster_mean [128,10000]
    if (n_in >= 2 && in_sizes[0] == DIM * N_EMBED) {  // defensive order check
        const float* t = A; A = Bm; Bm = t;
    }
    float* out = (float*)d_out;

    cnorm_kernel<<<N_EMBED_PAD / 64, 256>>>(Bm);
    prep_b_kernel<<<(DIM / 2) * N_EMBED_PAD / 256, 256>>>(Bm);

    const int smem_bytes = SMEM_WORDS * (int)sizeof(uint32_t);   // 104KB
    static int attr_set = 0;
    if (!attr_set) {
        cudaFuncSetAttribute(quantize_kernel,
                             cudaFuncAttributeMaxDynamicSharedMemorySize, smem_bytes);
        attr_set = 1;
    }
    quantize_kernel<<<128 * NSLICE, THREADS, smem_bytes>>>(A);
    combine_kernel<<<N_SAMPLES / 8, 256>>>(A, Bm, out);
}

// round 11
// speedup vs baseline: 2.4042x; 1.1267x over previous
#include <cuda_runtime.h>
#include <float.h>
#include <stdint.h>

#define DIM 128
#define N_SAMPLES 8192
#define N_EMBED 10000
#define N_EMBED_PAD 10240
#define TM 64
#define TN 64
#define BSTRIDE 72
#define THREADS 256
#define NSLICE 16
#define SLICE_W 640
#define NCH 10

typedef unsigned long long u64;

__device__ float    g_cnorm[N_EMBED_PAD];
__device__ u64      g_best[N_SAMPLES];
__device__ uint32_t g_bhi16[(DIM / 2) * N_EMBED_PAD];   // fp16x2 hi of cm, [k/2][j]
__device__ u64      g_t1[NSLICE * N_SAMPLES];           // per-slice top1 (packed)
__device__ float    g_t2[NSLICE * N_SAMPLES];           // per-slice top2 value
__device__ float    g_eps[N_SAMPLES];                   // sound error bound (2x folded)
__device__ unsigned g_maxbhi, g_maxblo;                 // max_j ||bhi||^2, ||blo||^2 bits
__device__ int      g_rescue_count;
__device__ int      g_rescue_list[N_SAMPLES];

__device__ __forceinline__ unsigned smem_u32(const void* p) {
    return (unsigned)__cvta_generic_to_shared(p);
}
__device__ __forceinline__ void cp16(unsigned dst, const void* src) {
    asm volatile("cp.async.cg.shared.global [%0], [%1], 16;" :: "r"(dst), "l"(src));
}
__device__ __forceinline__ void cp16z(unsigned dst, const void* src, int sz) {
    asm volatile("cp.async.cg.shared.global [%0], [%1], 16, %2;"
                 :: "r"(dst), "l"(src), "r"(sz));
}
__device__ __forceinline__ u64 enc_best(float v, int j) {
    unsigned b = __float_as_uint(v);
    b = ((int)b < 0) ? ~b : (b | 0x80000000u);
    return ((u64)b << 32) | (unsigned)(~j);
}
__device__ __forceinline__ float dec_val(u64 p) {
    unsigned b = (unsigned)(p >> 32);
    unsigned f = (b & 0x80000000u) ? (b ^ 0x80000000u) : ~b;
    return __uint_as_float(f);
}
// fp16 round-trip: returns fl16(v) as fp32, residual (exact, Sterbenz) in *lo.
__device__ __forceinline__ float f16rt(float v, float* lo) {
    unsigned short hb; float hf;
    asm("cvt.rn.f16.f32 %0, %1;" : "=h"(hb) : "f"(v));
    asm("cvt.f32.f16 %0, %1;"    : "=f"(hf) : "h"(hb));
    *lo = v - hf;
    return hf;
}
__device__ __forceinline__ void hsplit2hi(float x, float y, uint32_t& hw) {
    unsigned short hx, hy;
    asm("cvt.rn.f16.f32 %0, %1;" : "=h"(hx) : "f"(x));
    asm("cvt.rn.f16.f32 %0, %1;" : "=h"(hy) : "f"(y));
    hw = (uint32_t)hx | ((uint32_t)hy << 16);
}
__device__ __forceinline__ void mma_f16(float* d, uint4 a, uint32_t b0, uint32_t b1) {
    asm volatile(
        "mma.sync.aligned.m16n8k16.row.col.f32.f16.f16.f32 "
        "{%0,%1,%2,%3}, {%4,%5,%6,%7}, {%8,%9}, {%0,%1,%2,%3};"
        : "+f"(d[0]), "+f"(d[1]), "+f"(d[2]), "+f"(d[3])
        : "r"(a.x), "r"(a.y), "r"(a.z), "r"(a.w), "r"(b0), "r"(b1));
}

// ---------------- prep: cnorm + b-split norm maxes + counter reset ----------------
__global__ void cnorm_kernel(const float* __restrict__ cm) {
    __shared__ float red[3][4][64];
    __shared__ unsigned mhi, mlo;
    const int tid = threadIdx.x;
    const int jl  = tid & 63;
    const int dc  = tid >> 6;
    const int j   = blockIdx.x * 64 + jl;
    if (tid == 0) { mhi = 0; mlo = 0; }
    if (blockIdx.x == 0 && tid == 0) g_rescue_count = 0;
    __syncthreads();
    float s_cn = 0.f, s_hi = 0.f, s_lo = 0.f;
    if (j < N_EMBED) {
#pragma unroll 8
        for (int dd = 0; dd < 32; dd++) {
            float v = cm[(dc * 32 + dd) * N_EMBED + j];
            float lo, hf = f16rt(v, &lo);
            s_cn += v * v; s_hi += hf * hf; s_lo += lo * lo;
        }
    }
    red[0][dc][jl] = s_cn; red[1][dc][jl] = s_hi; red[2][dc][jl] = s_lo;
    __syncthreads();
    if (dc == 0) {
        float cn = red[0][0][jl] + red[0][1][jl] + red[0][2][jl] + red[0][3][jl];
        float hi = red[1][0][jl] + red[1][1][jl] + red[1][2][jl] + red[1][3][jl];
        float lo = red[2][0][jl] + red[2][1][jl] + red[2][2][jl] + red[2][3][jl];
        g_cnorm[j] = (j < N_EMBED) ? cn : -1e30f;
        if (j < N_EMBED) {
            atomicMax(&mhi, __float_as_uint(hi));
            atomicMax(&mlo, __float_as_uint(lo));
        }
    }
    __syncthreads();
    if (tid == 0) {  // deterministic across replays: same inputs -> same maxes
        atomicMax(&g_maxbhi, mhi);
        atomicMax(&g_maxblo, mlo);
    }
}

// Split cluster_mean hi halves, packed k-pairs [k/2][j] (zero pad).
__global__ void prep_b_kernel(const float* __restrict__ cm) {
    int idx = blockIdx.x * 256 + threadIdx.x;
    if (idx >= (DIM / 2) * N_EMBED_PAD) return;
    int kp = idx / N_EMBED_PAD, j = idx - kp * N_EMBED_PAD;
    float v0 = (j < N_EMBED) ? cm[(2 * kp) * N_EMBED + j] : 0.f;
    float v1 = (j < N_EMBED) ? cm[(2 * kp + 1) * N_EMBED + j] : 0.f;
    uint32_t hw; hsplit2hi(v0, v1, hw);
    g_bhi16[idx] = hw;
}

// Per-sample sound error bound (needs g_maxbhi/g_maxblo from cnorm_kernel).
__global__ void prep_aeps_kernel(const float* __restrict__ A) {
    const int w = threadIdx.x >> 5, lane = threadIdx.x & 31;
    const int s = blockIdx.x * 8 + w;
    float shi = 0.f, slo = 0.f;
#pragma unroll
    for (int r = 0; r < 4; r++) {
        float a = -2.f * A[s * DIM + lane + 32 * r];
        float lo, hf = f16rt(a, &lo);
        shi += hf * hf; slo += lo * lo;
    }
#pragma unroll
    for (int off = 16; off > 0; off >>= 1) {
        shi += __shfl_xor_sync(0xFFFFFFFFu, shi, off);
        slo += __shfl_xor_sync(0xFFFFFFFFu, slo, off);
    }
    if (lane == 0) {
        float MBHI = sqrtf(__uint_as_float(g_maxbhi));
        float MBLO = sqrtf(__uint_as_float(g_maxblo));
        float nlo = sqrtf(slo), nhi = sqrtf(shi);
        g_eps[s] = 2.0002f * (nlo * MBHI + nhi * MBLO + nlo * MBLO) + 0.02f;
    }
}

// ---------------- phase1: hi-only mma + per-slice top-2 ----------------
#define AW     4096
#define BHALF  (64 * BSTRIDE)     // 4608 words
#define SMEM_WORDS (AW + 2 * BHALF + 768)   // + merge scratch

__global__ __launch_bounds__(THREADS)
void phase1_kernel(const float* __restrict__ A) {
    extern __shared__ uint32_t smw[];
    uint32_t* Aw = smw;
    uint32_t* Bw = smw + AW;
    u64*   mt1 = (u64*)(smw + AW + 2 * BHALF);   // [4 wn][64 rows]
    float* mt2 = (float*)(smw + AW + 2 * BHALF + 512);

    const int tid  = threadIdx.x;
    const int lane = tid & 31;
    const int sy   = tid >> 5;
    const int wm   = sy >> 2;
    const int wn   = sy & 3;
    const int n0w  = wn * 16;
    const int mtg0 = wm * 2;
    const int tig  = lane & 3;
    const int bcol = lane >> 2;

    const int mt  = blockIdx.x & 127;
    const int sl  = blockIdx.x >> 7;
    const int m0  = mt * TM;
    const int j00 = sl * SLICE_W;

    auto issueB = [&](int t) {
        const int j0 = j00 + t * TN;
        uint32_t* dst = Bw + (t & 1) * BHALF;
        for (int i = tid; i < 1024; i += THREADS) {   // 4 iters
            int kp = i >> 4;
            int jj = (i & 15) * 4;
            cp16(smem_u32(dst + kp * BSTRIDE + jj),
                 g_bhi16 + (size_t)kp * N_EMBED_PAD + j0 + jj);
        }
        asm volatile("cp.async.commit_group;");
    };

    issueB(0);
    issueB(1);

    // A hi split, fragment-major.
    for (int i = tid; i < 1024; i += THREADS) {
        int li = i & 31;
        int ks = (i >> 5) & 7;
        int mq = i >> 8;
        int r = li >> 2, tg = li & 3;
        int row0 = m0 + mq * 16 + r;
        int c0 = ks * 16 + 2 * tg;
        const float* A0 = A + (size_t)row0 * DIM;
        const float* A1 = A0 + 8 * DIM;
        uint32_t h0, h1, h2, h3;
        hsplit2hi(-2.f * A0[c0],     -2.f * A0[c0 + 1], h0);
        hsplit2hi(-2.f * A1[c0],     -2.f * A1[c0 + 1], h1);
        hsplit2hi(-2.f * A0[c0 + 8], -2.f * A0[c0 + 9], h2);
        hsplit2hi(-2.f * A1[c0 + 8], -2.f * A1[c0 + 9], h3);
        *(uint4*)&Aw[((mq * 8 + ks) * 32 + li) * 4] = make_uint4(h0, h1, h2, h3);
    }

    float b1[4], b2[4];
    int   j1[4];
#pragma unroll
    for (int i = 0; i < 4; i++) { b1[i] = -FLT_MAX; b2[i] = -FLT_MAX; j1[i] = 0; }

    for (int t = 0; t < NCH; t++) {
        if (t < NCH - 1) asm volatile("cp.async.wait_group 1;");
        else             asm volatile("cp.async.wait_group 0;");
        __syncthreads();

        const uint32_t* bh = Bw + (t & 1) * BHALF;
        const int j0 = j00 + t * TN;

        float acc[2][2][4];
#pragma unroll
        for (int nt = 0; nt < 2; nt++) {
            int c0 = j0 + n0w + nt * 8 + 2 * tig;
            float cn0 = __ldg(&g_cnorm[c0]);
            float cn1 = __ldg(&g_cnorm[c0 + 1]);
#pragma unroll
            for (int mq = 0; mq < 2; mq++) {
                acc[mq][nt][0] = cn0; acc[mq][nt][1] = cn1;
                acc[mq][nt][2] = cn0; acc[mq][nt][3] = cn1;
            }
        }

#pragma unroll
        for (int ks = 0; ks < 8; ks++) {
            uint4 ah0 = *(const uint4*)&Aw[(((mtg0 + 0) * 8 + ks) * 32 + lane) * 4];
            uint4 ah1 = *(const uint4*)&Aw[(((mtg0 + 1) * 8 + ks) * 32 + lane) * 4];
            int kp0 = ks * 8 + tig;
            uint32_t bh00 = bh[kp0 * BSTRIDE + n0w + bcol];
            uint32_t bh01 = bh[(kp0 + 4) * BSTRIDE + n0w + bcol];
            uint32_t bh10 = bh[kp0 * BSTRIDE + n0w + 8 + bcol];
            uint32_t bh11 = bh[(kp0 + 4) * BSTRIDE + n0w + 8 + bcol];
            mma_f16(acc[0][0], ah0, bh00, bh01);
            mma_f16(acc[1][0], ah1, bh00, bh01);
            mma_f16(acc[0][1], ah0, bh10, bh11);
            mma_f16(acc[1][1], ah1, bh10, bh11);
        }

        // top-2 update (ascending j preserves first-occurrence for top1).
#pragma unroll
        for (int nt = 0; nt < 2; nt++) {
            int c0 = j0 + n0w + nt * 8 + 2 * tig;
#pragma unroll
            for (int mq = 0; mq < 2; mq++) {
#pragma unroll
                for (int rb = 0; rb < 2; rb++) {
                    int st = mq * 2 + rb;
                    float v0 = acc[mq][nt][rb * 2 + 0];
                    float v1 = acc[mq][nt][rb * 2 + 1];
                    if (v0 > b1[st]) { b2[st] = b1[st]; b1[st] = v0; j1[st] = c0; }
                    else if (v0 > b2[st]) b2[st] = v0;
                    if (v1 > b1[st]) { b2[st] = b1[st]; b1[st] = v1; j1[st] = c0 + 1; }
                    else if (v1 > b2[st]) b2[st] = v1;
                }
            }
        }

        __syncthreads();
        if (t + 2 < NCH) issueB(t + 2);
    }

    // quad merge (4 lanes share rows), stash per-wn, then cross-warp merge.
#pragma unroll
    for (int s = 0; s < 4; s++) {
        float v = b1[s], v2 = b2[s];
        int   bj = j1[s];
#pragma unroll
        for (int off = 1; off < 4; off <<= 1) {
            float ov  = __shfl_xor_sync(0xFFFFFFFFu, v, off);
            int   oj  = __shfl_xor_sync(0xFFFFFFFFu, bj, off);
            float ov2 = __shfl_xor_sync(0xFFFFFFFFu, v2, off);
            float nv2 = fmaxf(fmaxf(v2, ov2), fminf(v, ov));
            if (ov > v || (ov == v && oj < bj)) { v = ov; bj = oj; }
            v2 = nv2;
        }
        if ((lane & 3) == 0) {
            int mq = s >> 1, rb = s & 1;
            int rl = (mtg0 + mq) * 16 + (lane >> 2) + rb * 8;   // 0..63
            mt1[wn * 64 + rl] = enc_best(v, bj);
            mt2[wn * 64 + rl] = v2;
        }
    }
    __syncthreads();
    if (tid < 64) {
        int r = tid;
        u64 m = mt1[r]; int wi = 0;
        for (int w = 1; w < 4; w++) {
            u64 t = mt1[w * 64 + r];
            if (t > m) { m = t; wi = w; }
        }
        float v2 = -FLT_MAX;
        for (int w = 0; w < 4; w++) {
            float c = (w == wi) ? mt2[w * 64 + r]
                                : fmaxf(dec_val(mt1[w * 64 + r]), mt2[w * 64 + r]);
            v2 = fmaxf(v2, c);
        }
        g_t1[sl * N_SAMPLES + m0 + r] = m;
        g_t2[sl * N_SAMPLES + m0 + r] = v2;
    }
}

// ---------------- combine: global top-2, gap test, rescue list ----------------
__global__ void combine_kernel() {
    const int s = blockIdx.x * 256 + threadIdx.x;
    u64 m1 = 0; int i1 = 0;
#pragma unroll
    for (int i = 0; i < NSLICE; i++) {
        u64 t = g_t1[i * N_SAMPLES + s];
        if (t > m1) { m1 = t; i1 = i; }
    }
    float v1 = dec_val(m1);
    float v2 = -FLT_MAX;
#pragma unroll
    for (int i = 0; i < NSLICE; i++) {
        float c = (i == i1) ? g_t2[i * N_SAMPLES + s]
                            : fmaxf(dec_val(g_t1[i * N_SAMPLES + s]),
                                    g_t2[i * N_SAMPLES + s]);
        v2 = fmaxf(v2, c);
    }
    if (v1 - v2 > g_eps[s]) {
        g_best[s] = m1;                       // provably exact argmax
    } else {
        g_best[s] = 0;
        int p = atomicAdd(&g_rescue_count, 1);
        g_rescue_list[p] = s;
    }
}

// ---------------- rescue: exact fp32 re-scan for contested samples ----------------
#define RS_AW 4096                     // 128k x 32s floats
#define RS_BW 16384                    // 128k x 128j floats per buffer
__global__ __launch_bounds__(256)
void rescue_kernel(const float* __restrict__ A, const float* __restrict__ Bm) {
    const int cnt = *(volatile int*)&g_rescue_count;
    const int sb = blockIdx.x >> 3, sl = blockIdx.x & 7;
    if (sb * 32 >= cnt) return;
    const int nval = min(32, cnt - sb * 32);

    extern __shared__ float smf[];
    float* As = smf;                       // [128k][32s]
    float* Bs = smf + RS_AW;               // 2 x [128k][128j]

    const int tid = threadIdx.x, lane = tid & 31, w = tid >> 5;
    const int j00 = sl * 1280;

    auto issueB = [&](int t) {
        const int j0 = j00 + t * 128;
        float* dst = Bs + (t & 1) * RS_BW;
        for (int i = tid; i < 4096; i += 256) {   // 16 iters
            int k = i >> 5, j4 = (i & 31) * 4;
            int j = j0 + j4;
            cp16z(smem_u32(dst + k * 128 + j4),
                  Bm + (size_t)k * N_EMBED + min(j, N_EMBED - 4),
                  (j < N_EMBED) ? 16 : 0);
        }
        asm volatile("cp.async.commit_group;");
    };

    issueB(0);
    issueB(1);

    // Load rescue sample rows, transposed, -2 folded.
    for (int i = tid; i < 1024; i += 256) {
        int si = i >> 5, k4 = (i & 31) * 4;
        float4 v = make_float4(0.f, 0.f, 0.f, 0.f);
        if (si < nval) {
            int s = g_rescue_list[sb * 32 + si];
            v = *(const float4*)&A[(size_t)s * DIM + k4];
        }
        As[(k4 + 0) * 32 + si] = -2.f * v.x;
        As[(k4 + 1) * 32 + si] = -2.f * v.y;
        As[(k4 + 2) * 32 + si] = -2.f * v.z;
        As[(k4 + 3) * 32 + si] = -2.f * v.w;
    }

    float bestv[4]; int bestj[4];
#pragma unroll
    for (int i = 0; i < 4; i++) { bestv[i] = -FLT_MAX; bestj[i] = 0; }

    for (int t = 0; t < 10; t++) {
        if (t < 9) asm volatile("cp.async.wait_group 1;");
        else       asm volatile("cp.async.wait_group 0;");
        __syncthreads();
        const float* bp = Bs + (t & 1) * RS_BW;
        const int j0 = j00 + t * 128;

        float acc[4][4];
#pragma unroll
        for (int g = 0; g < 4; g++) {
            float cn = __ldg(&g_cnorm[j0 + lane + 32 * g]);
#pragma unroll
            for (int si = 0; si < 4; si++) acc[si][g] = cn;
        }
#pragma unroll 4
        for (int k = 0; k < DIM; k++) {
            float4 a4 = *(const float4*)&As[k * 32 + 4 * w];
            float a[4] = {a4.x, a4.y, a4.z, a4.w};
#pragma unroll
            for (int g = 0; g < 4; g++) {
                float b = bp[k * 128 + lane + 32 * g];
#pragma unroll
                for (int si = 0; si < 4; si++) acc[si][g] = fmaf(a[si], b, acc[si][g]);
            }
        }
#pragma unroll
        for (int g = 0; g < 4; g++) {
            int j = j0 + lane + 32 * g;
#pragma unroll
            for (int si = 0; si < 4; si++) {
                if (acc[si][g] > bestv[si]) { bestv[si] = acc[si][g]; bestj[si] = j; }
            }
        }
        __syncthreads();
        if (t + 2 < 10) issueB(t + 2);
    }

#pragma unroll
    for (int si = 0; si < 4; si++) {
        float v = bestv[si]; int bj = bestj[si];
#pragma unroll
        for (int off = 16; off > 0; off >>= 1) {
            float ov = __shfl_xor_sync(0xFFFFFFFFu, v, off);
            int   oj = __shfl_xor_sync(0xFFFFFFFFu, bj, off);
            if (ov > v || (ov == v && oj < bj)) { v = ov; bj = oj; }
        }
        int gi = 4 * w + si;
        if (lane == 0 && gi < nval)
            atomicMax(&g_best[g_rescue_list[sb * 32 + gi]], enc_best(v, bj));
    }
}

// ---------------- gather: quantize/index/diff outputs ----------------
__global__ void gather_kernel(const float* __restrict__ A,
                              const float* __restrict__ Bm,
                              float* __restrict__ out) {
    const int w = threadIdx.x >> 5, lane = threadIdx.x & 31;
    const int s = blockIdx.x * 8 + w;
    const int j = (int)(unsigned)(~(unsigned)g_best[s]);
    float sum = 0.f;
#pragma unroll
    for (int r = 0; r < 4; r++) {
        const int d = lane + r * 32;
        float q = __ldg(&Bm[d * N_EMBED + j]);
        out[s * DIM + d] = q;
        float x = A[s * DIM + d];
        float t = x - q;
        sum += t * t;
    }
#pragma unroll
    for (int off = 16; off > 0; off >>= 1)
        sum += __shfl_xor_sync(0xFFFFFFFFu, sum, off);
    if (lane == 0) {
        out[N_SAMPLES * DIM + s] = (float)j;
        out[N_SAMPLES * (DIM + 1) + s] = sum * (1.0f / DIM);
    }
}

extern "C" void kernel_launch(void* const* d_in, const int* in_sizes, int n_in,
                              void* d_out, int out_size) {
    const float* A  = (const float*)d_in[0];
    const float* Bm = (const float*)d_in[1];
    if (n_in >= 2 && in_sizes[0] == DIM * N_EMBED) {
        const float* t = A; A = Bm; Bm = t;
    }
    float* out = (float*)d_out;

    static int attr_set = 0;
    if (!attr_set) {
        cudaFuncSetAttribute(phase1_kernel,
            cudaFuncAttributeMaxDynamicSharedMemorySize, SMEM_WORDS * 4);
        cudaFuncSetAttribute(rescue_kernel,
            cudaFuncAttributeMaxDynamicSharedMemorySize, (RS_AW + 2 * RS_BW) * 4);
        attr_set = 1;
    }

    cnorm_kernel<<<N_EMBED_PAD / 64, 256>>>(Bm);
    prep_b_kernel<<<(DIM / 2) * N_EMBED_PAD / 256, 256>>>(Bm);
    prep_aeps_kernel<<<N_SAMPLES / 8, 256>>>(A);
    phase1_kernel<<<128 * NSLICE, THREADS, SMEM_WORDS * 4>>>(A);
    combine_kernel<<<N_SAMPLES / 256, 256>>>();
    rescue_kernel<<<2048, 256, (RS_AW + 2 * RS_BW) * 4>>>(A, Bm);
    gather_kernel<<<N_SAMPLES / 8, 256>>>(A, Bm, out);
}